// round 1
// baseline (speedup 1.0000x reference)
#include <cuda_runtime.h>

// Shapes: h (2,512,256) f32, W (128,512) f32, b (128,) f32
// out (2,512,512,128) f32 = 256 MB  -> store-bandwidth bound.
#define B_   2
#define L_   512
#define D_   256
#define P_   128
#define BL_  (B_ * L_)   // 1024

// Scratch for the two projections (p1 has bias folded in).
__device__ float g_p1[BL_ * P_];
__device__ float g_p2[BL_ * P_];

// ---------------------------------------------------------------------------
// proj_kernel: p1[bi,p] = sum_d h[bi,d]*W[p,d] + bias[p]
//              p2[bi,p] = sum_d h[bi,d]*W[p,D+d]
// Block = 256 threads handles 8 rows of h. threads split: p = tid&127,
// half = tid>>7 selects W1 vs W2. h rows staged in shared (float4).
// ---------------------------------------------------------------------------
__global__ void __launch_bounds__(256) proj_kernel(
    const float4* __restrict__ h4,     // BL_ x 64 float4
    const float4* __restrict__ W4,     // P_ x 128 float4 (512 floats per row)
    const float*  __restrict__ bias)
{
    __shared__ float4 sh[8 * 64];      // 8 rows x 256 floats
    const int row0 = blockIdx.x * 8;

    for (int t = threadIdx.x; t < 8 * 64; t += 256)
        sh[t] = h4[row0 * 64 + t];
    __syncthreads();

    const int p    = threadIdx.x & 127;
    const int half = threadIdx.x >> 7;           // 0 -> W1, 1 -> W2
    const float4* wrow = W4 + p * 128 + half * 64;

    float acc[8];
#pragma unroll
    for (int r = 0; r < 8; r++) acc[r] = 0.f;

#pragma unroll 4
    for (int k = 0; k < 64; k++) {
        float4 w = wrow[k];
#pragma unroll
        for (int r = 0; r < 8; r++) {
            float4 hv = sh[r * 64 + k];
            acc[r] += hv.x * w.x + hv.y * w.y + hv.z * w.z + hv.w * w.w;
        }
    }

    const float bb  = half ? 0.f : bias[p];
    float* dst = half ? g_p2 : g_p1;
#pragma unroll
    for (int r = 0; r < 8; r++)
        dst[(row0 + r) * P_ + p] = acc[r] + bb;
}

// ---------------------------------------------------------------------------
// bcast_kernel: out[b,i,j,p] = p1[b,i,p] + p2[b,j,p]   (bias already in p1)
// Block = 256 threads owns an 8-i x 64-j tile for one batch b.
//   - p2 tile (64 rows x 512B = 32 KB) staged in shared, reused by all 8 i's.
//   - each warp owns one i: p1 row in registers, loops 64 j's.
//   - stores: 512 B contiguous per warp per j -> fully coalesced float4 STG.
// Grid = (BL_/8, L_/64) = (128, 8) -> 1024 blocks, 256 KB stores each.
// ---------------------------------------------------------------------------
__global__ void __launch_bounds__(256) bcast_kernel(float4* __restrict__ out)
{
    __shared__ float4 s2[64 * 32];               // 64 j-rows x 32 float4

    const int bi0 = blockIdx.x * 8;              // first of 8 i-rows (bi = b*L_+i)
    const int b   = bi0 >> 9;                    // / L_
    const int jb  = blockIdx.y * 64;

    const float4* p14 = (const float4*)g_p1;
    const float4* p24 = (const float4*)g_p2;

    // stage p2 tile: rows [jb, jb+64) of batch b
    const float4* p2src = p24 + ((b << 9) + jb) * 32;
    for (int t = threadIdx.x; t < 64 * 32; t += 256)
        s2[t] = p2src[t];
    __syncthreads();

    const int p4 = threadIdx.x & 31;             // float4 index within the 128-p row
    const int w  = threadIdx.x >> 5;             // warp id 0..7 -> local i

    const float4 a = p14[(bi0 + w) * 32 + p4];   // p1 row chunk, reused 64x

    float4* orow = out + ((size_t)(bi0 + w) * L_ + jb) * 32 + p4;

#pragma unroll 8
    for (int j = 0; j < 64; j++) {
        float4 c = s2[j * 32 + p4];
        float4 r = make_float4(a.x + c.x, a.y + c.y, a.z + c.z, a.w + c.w);
        orow[(size_t)j * 32] = r;
    }
}

extern "C" void kernel_launch(void* const* d_in, const int* in_sizes, int n_in,
                              void* d_out, int out_size)
{
    const float* h    = (const float*)d_in[0];   // 2*512*256
    const float* W    = (const float*)d_in[1];   // 128*512
    const float* bias = (const float*)d_in[2];   // 128

    proj_kernel<<<BL_ / 8, 256>>>((const float4*)h, (const float4*)W, bias);
    bcast_kernel<<<dim3(BL_ / 8, L_ / 64), 256>>>((float4*)d_out);
}

// round 4
// speedup vs baseline: 1.1669x; 1.1669x over previous
#include <cuda_runtime.h>

// Shapes: h (2,512,256) f32, W (128,512) f32, b (128,) f32
// out (2,512,512,128) f32 = 256 MB  -> store-bandwidth bound.
#define B_   2
#define L_   512
#define D_   256
#define P_   128
#define BL_  (B_ * L_)   // 1024

// Scratch for the two projections (p1 has bias folded in).
__device__ float g_p1[BL_ * P_];
__device__ float g_p2[BL_ * P_];

// ---------------------------------------------------------------------------
// proj_kernel v2: 128 blocks x 512 threads, 8 h-rows per block.
// Threads: p = tid&127, half = (tid>>7)&1 (W1 vs W2), kh = tid>>8 (k-split).
// Each thread does a 128-length partial dot (32 float4 k-steps); kh=1 partials
// are reduced into kh=0 via shared. 16 warps/SM for latency hiding; W read
// once per block (32 MB L2 traffic total).
// ---------------------------------------------------------------------------
__global__ void __launch_bounds__(512) proj_kernel(
    const float4* __restrict__ h4,     // BL_ x 64 float4
    const float4* __restrict__ W4,     // P_ x 128 float4 (512 floats per row)
    const float*  __restrict__ bias)
{
    __shared__ float4 sh[8 * 64];      // 8 rows x 256 floats (8 KB)
    __shared__ float  spart[256 * 8];  // partials from kh=1 (8 KB)

    const int row0 = blockIdx.x * 8;
    sh[threadIdx.x] = h4[row0 * 64 + threadIdx.x];   // exactly 512 float4
    __syncthreads();

    const int p    = threadIdx.x & 127;
    const int half = (threadIdx.x >> 7) & 1;         // 0 -> W1, 1 -> W2
    const int kh   = threadIdx.x >> 8;               // k-half
    const int ph   = threadIdx.x & 255;              // (half,p) id

    const float4* wrow = W4 + p * 128 + half * 64 + kh * 32;
    const float4* hsh  = sh + kh * 32;

    float acc[8];
#pragma unroll
    for (int r = 0; r < 8; r++) acc[r] = 0.f;

#pragma unroll 4
    for (int k = 0; k < 32; k++) {
        float4 w = wrow[k];
#pragma unroll
        for (int r = 0; r < 8; r++) {
            float4 hv = hsh[r * 64 + k];
            acc[r] += hv.x * w.x + hv.y * w.y + hv.z * w.z + hv.w * w.w;
        }
    }

    if (kh == 1) {
#pragma unroll
        for (int r = 0; r < 8; r++) spart[ph * 8 + r] = acc[r];
    }
    __syncthreads();
    if (kh == 0) {
        const float bb = half ? 0.f : bias[p];
        float* dst = half ? g_p2 : g_p1;
#pragma unroll
        for (int r = 0; r < 8; r++)
            dst[(row0 + r) * P_ + p] = acc[r] + spart[ph * 8 + r] + bb;
    }
}

// ---------------------------------------------------------------------------
// bcast_kernel v2: out[b,i,j,p] = p1[b,i,p] + p2[b,j,p] (bias in p1).
// Block = 256 threads owns an 8-i x 32-j tile (16 KB smem -> ~2x occupancy
// vs 32 KB). Each warp owns one i; p1 chunk in registers; 32 fully-unrolled
// independent coalesced 512B stores per warp via __stcs (evict-first
// streaming: output never pollutes L2, p2 stays resident).
// Grid = (128, 16) = 2048 blocks, 128 KB stores each.
// ---------------------------------------------------------------------------
__global__ void __launch_bounds__(256) bcast_kernel(float4* __restrict__ out)
{
    __shared__ float4 s2[32 * 32];               // 32 j-rows x 32 float4 (16 KB)

    const int bi0 = blockIdx.x * 8;              // first of 8 i-rows (bi = b*L_+i)
    const int b   = bi0 >> 9;                    // / L_
    const int jb  = blockIdx.y * 32;

    const float4* p14 = (const float4*)g_p1;
    const float4* p24 = (const float4*)g_p2;

    // stage p2 tile: rows [jb, jb+32) of batch b (L2-resident source)
    const float4* p2src = p24 + ((b << 9) + jb) * 32;
#pragma unroll
    for (int t = 0; t < 4; t++)
        s2[t * 256 + threadIdx.x] = p2src[t * 256 + threadIdx.x];
    __syncthreads();

    const int p4 = threadIdx.x & 31;             // float4 index within 128-p row
    const int w  = threadIdx.x >> 5;             // warp id 0..7 -> local i

    const float4 a = p14[(bi0 + w) * 32 + p4];   // p1 row chunk, reused 32x

    float4* orow = out + ((size_t)(bi0 + w) * L_ + jb) * 32 + p4;

#pragma unroll
    for (int j = 0; j < 32; j++) {
        float4 c = s2[j * 32 + p4];
        float4 r = make_float4(a.x + c.x, a.y + c.y, a.z + c.z, a.w + c.w);
        __stcs(orow + (size_t)j * 32, r);
    }
}

extern "C" void kernel_launch(void* const* d_in, const int* in_sizes, int n_in,
                              void* d_out, int out_size)
{
    const float* h    = (const float*)d_in[0];   // 2*512*256
    const float* W    = (const float*)d_in[1];   // 128*512
    const float* bias = (const float*)d_in[2];   // 128

    proj_kernel<<<BL_ / 8, 512>>>((const float4*)h, (const float4*)W, bias);
    bcast_kernel<<<dim3(BL_ / 8, L_ / 32), 256>>>((float4*)d_out);
}